// round 6
// baseline (speedup 1.0000x reference)
#include <cuda_runtime.h>
#include <cstdint>
#include <math.h>

#define NT 512
#define TILE 64
#define G_OFF    25344        // seg1 size: 192*132 floats
#define SMEM_FLOATS 37888     // seg1 + G (64*196)  = 151552 bytes

// Pre-converted tf32 weights, permuted per-k8-chunk N-major (filled by prep_weights)
#define W1S_OFF   0
#define W2S_OFF   114688
#define W1V1_OFF  180224
#define W2V1_OFF  196608
#define W1V2_OFF  212992
#define W2V2_OFF  217088
#define WBUF_SZ   221184
__device__ float WBUF[WBUF_SZ];

static __device__ __forceinline__ float f2tff(float f){
  uint32_t u; asm("cvt.rna.tf32.f32 %0, %1;" : "=r"(u) : "f"(f));
  return __uint_as_float(u);
}

static __device__ __forceinline__ void mma8(float* d, uint32_t a0, uint32_t a1,
                                            uint32_t a2, uint32_t a3,
                                            uint32_t b0, uint32_t b1){
  asm volatile("mma.sync.aligned.m16n8k8.row.col.f32.tf32.tf32.f32 "
      "{%0,%1,%2,%3}, {%4,%5,%6,%7}, {%8,%9}, {%0,%1,%2,%3};"
      : "+f"(d[0]), "+f"(d[1]), "+f"(d[2]), "+f"(d[3])
      : "r"(a0), "r"(a1), "r"(a2), "r"(a3), "r"(b0), "r"(b1));
}

// One ldmatrix.x4 = whole 16x8 tf32 A fragment (a0..a3) for one m16 tile.
static __device__ __forceinline__ void ldsm4(uint32_t* r, uint32_t addr){
  asm volatile("ldmatrix.sync.aligned.m8n8.x4.shared.b16 {%0,%1,%2,%3}, [%4];"
      : "=r"(r[0]), "=r"(r[1]), "=r"(r[2]), "=r"(r[3]) : "r"(addr));
}

// ---------------------------------------------------------------------------
// Init kernel: tf32-convert + permute weights into k8-chunked N-major layout:
//   WBUF[off + kc*N*8 + n*8 + w] = tf32( W[(kc*8 + (w&1)*4 + (w>>1)) * N + n] )
// ---------------------------------------------------------------------------
__global__ void prep_weights(const float* __restrict__ w1s,
                             const float* __restrict__ w1v1,
                             const float* __restrict__ w1v2,
                             const float* __restrict__ w2s,
                             const float* __restrict__ w2v1,
                             const float* __restrict__ w2v2)
{
  int idx = blockIdx.x * blockDim.x + threadIdx.x;
  if (idx >= WBUF_SZ) return;
  const float* src; int N, loc;
  if      (idx < W2S_OFF)  { src = w1s;  N = 448; loc = idx - W1S_OFF;  }
  else if (idx < W1V1_OFF) { src = w2s;  N = 256; loc = idx - W2S_OFF;  }
  else if (idx < W2V1_OFF) { src = w1v1; N = 128; loc = idx - W1V1_OFF; }
  else if (idx < W1V2_OFF) { src = w2v1; N = 128; loc = idx - W2V1_OFF; }
  else if (idx < W2V2_OFF) { src = w1v2; N = 64;  loc = idx - W1V2_OFF; }
  else                     { src = w2v2; N = 64;  loc = idx - W2V2_OFF; }
  int kc = loc / (N*8); int r = loc - kc*N*8; int n = r >> 3; int w = r & 7;
  int k = kc*8 + (w&1)*4 + (w>>1);
  WBUF[idx] = f2tff(src[k*N + n]);
}

// ---------------------------------------------------------------------------
// acc += A(SMEM tf32, pitch PA, ldmatrix.x4, distance-1 pipe)
//      @ B(WBUF k8-packed, LDG.64, distance-2 pipe / 3 rotating stages).
// Fully unrolled k-loop -> all stage indices static. No barriers inside.
// ---------------------------------------------------------------------------
template<int K, int N, int WM, int WN, int PA>
static __device__ __forceinline__ void run_gemm(const float* __restrict__ gB,
                  uint32_t As_u32, float* acc, int lane, int mi, int nj)
{
  constexpr int NK8 = K/8;
  const float2* __restrict__ bp = reinterpret_cast<const float2*>(gB)
      + (lane & 3) + ((nj*WN)*8 + (lane>>2))*4;
  const int g = lane >> 3, r = lane & 7;
  const uint32_t aaddr = As_u32
      + ((uint32_t)(((mi*WM)*16 + r + (g&1)*8)*PA + (g>>1)*4))*4u;

  float2   b[3][WN];
  uint32_t a[2][WM][4];
  // prologue: B for steps 0 and 1, A for step 0
  #pragma unroll
  for (int wn=0; wn<WN; wn++) b[0][wn] = __ldg(bp + wn*32);
  #pragma unroll
  for (int wn=0; wn<WN; wn++) b[1][wn] = __ldg(bp + N*4 + wn*32);
  #pragma unroll
  for (int wm=0; wm<WM; wm++) ldsm4(a[0][wm], aaddr + wm*(16*PA*4));

  #pragma unroll
  for (int kc=0; kc<NK8; kc++){
    const int cur = kc % 3;
    if (kc+2 < NK8){
      #pragma unroll
      for (int wn=0; wn<WN; wn++)
        b[(kc+2)%3][wn] = __ldg(bp + (kc+2)*(N*4) + wn*32);
    }
    if (kc+1 < NK8){
      #pragma unroll
      for (int wm=0; wm<WM; wm++)
        ldsm4(a[(kc+1)&1][wm], aaddr + wm*(16*PA*4) + (kc+1)*32);
    }
    #pragma unroll
    for (int wn=0; wn<WN; wn++){
      uint32_t b0 = __float_as_uint(b[cur][wn].x);
      uint32_t b1 = __float_as_uint(b[cur][wn].y);
      #pragma unroll
      for (int wm=0; wm<WM; wm++)
        mma8(acc+(wm*WN+wn)*4, a[kc&1][wm][0],a[kc&1][wm][1],
             a[kc&1][wm][2],a[kc&1][wm][3], b0, b1);
    }
  }
}

static __device__ __forceinline__ float sspf(float v, float cssp){
  float sp = fmaxf(v, 0.0f) + log1pf(expf(-fabsf(v)));
  return cssp * (sp - 0.69314718055994531f);
}

__global__ void __launch_bounds__(NT, 1)
resblk_kernel(const float* __restrict__ x, float* __restrict__ out, float cssp)
{
  extern __shared__ float sm[];
  float* seg1 = sm;
  float* G    = sm + G_OFF;
  uint32_t sm_u32;
  { uint32_t a; asm("{ .reg .u64 t; cvta.to.shared.u64 t, %1; cvt.u32.u64 %0, t; }"
                    : "=r"(a) : "l"(sm)); sm_u32 = a; }

  const int tid  = threadIdx.x;
  const int lane = tid & 31;
  const int warp = tid >> 5;
  const int mi2  = warp & 1;      // 2M x 8N grid (scalar-path GEMMs)
  const int nj2  = warp >> 1;
  const int mi4  = warp >> 2;     // 4M x 4N grid (vector-path GEMMs)
  const int nj4  = warp & 3;
  const int n0   = blockIdx.x * TILE;
  const float RS128 = 0.08838834764831845f;
  const float RS64  = 0.125f;

  // ================= scalar path =================
  // A0 = tf32(x0 tile)  [64 x 256], pitch 260
  for (int t=tid; t<(TILE*256)/4; t+=NT){
    int e=t*4; int ln=e>>8; int col=e&255;
    float4 v = *reinterpret_cast<const float4*>(x + (size_t)(n0+ln)*960 + col);
    *reinterpret_cast<float4*>(seg1 + ln*260 + col) =
      make_float4(f2tff(v.x),f2tff(v.y),f2tff(v.z),f2tff(v.w));
  }
  __syncthreads();
  // s = A0 @ w1s / 16, SSP -> scalars(seg1, tf32) + gates(G, fp32)
  {
    float acc[56];
    #pragma unroll
    for (int i=0;i<56;i++) acc[i]=0.f;
    run_gemm<256,448,2,7,260>(&WBUF[W1S_OFF], sm_u32, acc, lane, mi2, nj2);
    __syncthreads();
    #pragma unroll
    for (int wm=0; wm<2; wm++){
      #pragma unroll
      for (int wn=0; wn<7; wn++){
        #pragma unroll
        for (int q=0;q<4;q++){
          int row = (mi2*2+wm)*16 + (lane>>2) + ((q&2)<<2);
          int col = (nj2*7+wn)*8 + ((lane&3)<<1) + (q&1);
          float h = sspf(acc[(wm*7+wn)*4+q]*0.0625f, cssp);
          if (col < 256) seg1[row*260 + col] = f2tff(h);
          else           G[row*196 + (col-256)] = h;
        }
      }
    }
  }
  __syncthreads();
  // y0 = scalars @ w2s / 16 ; stage then coalesced residual write
  {
    float acc[32];
    #pragma unroll
    for (int i=0;i<32;i++) acc[i]=0.f;
    run_gemm<256,256,2,4,260>(&WBUF[W2S_OFF], sm_u32, acc, lane, mi2, nj2);
    __syncthreads();
    #pragma unroll
    for (int wm=0; wm<2; wm++){
      #pragma unroll
      for (int wn=0; wn<4; wn++){
        #pragma unroll
        for (int q=0;q<4;q++){
          int row = (mi2*2+wm)*16 + (lane>>2) + ((q&2)<<2);
          int col = (nj2*4+wn)*8 + ((lane&3)<<1) + (q&1);
          seg1[row*260 + col] = acc[(wm*4+wn)*4+q]*0.0625f;
        }
      }
    }
    __syncthreads();
    for (int t=tid; t<TILE*64; t+=NT){
      int ln=t>>6; int j=(t&63)*4;
      size_t off = (size_t)(n0+ln)*960 + j;
      float4 xr = *reinterpret_cast<const float4*>(x + off);
      float4 yv = *reinterpret_cast<const float4*>(seg1 + ln*260 + j);
      *reinterpret_cast<float4*>(out + off) =
        make_float4(xr.x+yv.x, xr.y+yv.y, xr.z+yv.z, xr.w+yv.w);
    }
  }
  __syncthreads();

  // ================= v1 path =================
  // A1[c*64+n][i] = tf32(x[n, 256+3i+c])  [192 x 128], pitch 132
  for (int t=tid; t<(TILE*384)/4; t+=NT){
    int e=t*4; int ln=e/384; int j=e-ln*384;
    float4 v = *reinterpret_cast<const float4*>(x + (size_t)(n0+ln)*960 + 256 + j);
    float vv[4]={v.x,v.y,v.z,v.w};
    #pragma unroll
    for (int q=0;q<4;q++){
      int jj=j+q; int i3=jj/3; int c=jj-i3*3;
      seg1[(c*64+ln)*132 + i3] = f2tff(vv[q]);
    }
  }
  __syncthreads();
  // V1 = A1 @ w1v1 * rs128, gated, in place (tf32)
  {
    float acc[48];
    #pragma unroll
    for (int i=0;i<48;i++) acc[i]=0.f;
    run_gemm<128,128,3,4,132>(&WBUF[W1V1_OFF], sm_u32, acc, lane, mi4, nj4);
    __syncthreads();
    #pragma unroll
    for (int wm=0; wm<3; wm++){
      #pragma unroll
      for (int wn=0; wn<4; wn++){
        #pragma unroll
        for (int q=0;q<4;q++){
          int row = (mi4*3+wm)*16 + (lane>>2) + ((q&2)<<2);
          int col = (nj4*4+wn)*8 + ((lane&3)<<1) + (q&1);
          float g = G[(row&63)*196 + col];
          seg1[row*132 + col] = f2tff(acc[(wm*4+wn)*4+q]*RS128*g);
        }
      }
    }
  }
  __syncthreads();
  // Y1 = V1 @ w2v1 * rs128 -> stage [n][3o+c] -> coalesced residual write
  {
    float acc[48];
    #pragma unroll
    for (int i=0;i<48;i++) acc[i]=0.f;
    run_gemm<128,128,3,4,132>(&WBUF[W2V1_OFF], sm_u32, acc, lane, mi4, nj4);
    __syncthreads();
    #pragma unroll
    for (int wm=0; wm<3; wm++){
      #pragma unroll
      for (int wn=0; wn<4; wn++){
        #pragma unroll
        for (int q=0;q<4;q++){
          int row = (mi4*3+wm)*16 + (lane>>2) + ((q&2)<<2);
          int col = (nj4*4+wn)*8 + ((lane&3)<<1) + (q&1);
          int n = row & 63; int c = row >> 6;
          seg1[n*388 + 3*col + c] = acc[(wm*4+wn)*4+q]*RS128;
        }
      }
    }
    __syncthreads();
    for (int t=tid; t<TILE*96; t+=NT){
      int ln=t/96; int j=(t-ln*96)*4;
      size_t off = (size_t)(n0+ln)*960 + 256 + j;
      float4 xr = *reinterpret_cast<const float4*>(x + off);
      float4 yv = *reinterpret_cast<const float4*>(seg1 + ln*388 + j);
      *reinterpret_cast<float4*>(out + off) =
        make_float4(xr.x+yv.x, xr.y+yv.y, xr.z+yv.z, xr.w+yv.w);
    }
  }
  __syncthreads();

  // ================= v2 path =================
  // A2[c*64+n][i] = tf32(x[n, 640+5i+c])  [320 x 64], pitch 68
  for (int t=tid; t<(TILE*320)/4; t+=NT){
    int e=t*4; int ln=e/320; int j=e-ln*320;
    float4 v = *reinterpret_cast<const float4*>(x + (size_t)(n0+ln)*960 + 640 + j);
    float vv[4]={v.x,v.y,v.z,v.w};
    #pragma unroll
    for (int q=0;q<4;q++){
      int jj=j+q; int i5=jj/5; int c=jj-i5*5;
      seg1[(c*64+ln)*68 + i5] = f2tff(vv[q]);
    }
  }
  __syncthreads();
  // V2 = A2 @ w1v2 * rs64, gated, in place (tf32)
  {
    float acc[40];
    #pragma unroll
    for (int i=0;i<40;i++) acc[i]=0.f;
    run_gemm<64,64,5,2,68>(&WBUF[W1V2_OFF], sm_u32, acc, lane, mi4, nj4);
    __syncthreads();
    #pragma unroll
    for (int wm=0; wm<5; wm++){
      #pragma unroll
      for (int wn=0; wn<2; wn++){
        #pragma unroll
        for (int q=0;q<4;q++){
          int row = (mi4*5+wm)*16 + (lane>>2) + ((q&2)<<2);
          int col = (nj4*2+wn)*8 + ((lane&3)<<1) + (q&1);
          float g = G[(row&63)*196 + 128 + col];
          seg1[row*68 + col] = f2tff(acc[(wm*2+wn)*4+q]*RS64*g);
        }
      }
    }
  }
  __syncthreads();
  // Y2 = V2 @ w2v2 * rs64 -> stage [n][5o+c] -> coalesced residual write
  {
    float acc[40];
    #pragma unroll
    for (int i=0;i<40;i++) acc[i]=0.f;
    run_gemm<64,64,5,2,68>(&WBUF[W2V2_OFF], sm_u32, acc, lane, mi4, nj4);
    __syncthreads();
    #pragma unroll
    for (int wm=0; wm<5; wm++){
      #pragma unroll
      for (int wn=0; wn<2; wn++){
        #pragma unroll
        for (int q=0;q<4;q++){
          int row = (mi4*5+wm)*16 + (lane>>2) + ((q&2)<<2);
          int col = (nj4*2+wn)*8 + ((lane&3)<<1) + (q&1);
          int n = row & 63; int c = row >> 6;
          seg1[n*324 + 5*col + c] = acc[(wm*2+wn)*4+q]*RS64;
        }
      }
    }
    __syncthreads();
    for (int t=tid; t<TILE*80; t+=NT){
      int ln=t/80; int j=(t-ln*80)*4;
      size_t off = (size_t)(n0+ln)*960 + 640 + j;
      float4 xr = *reinterpret_cast<const float4*>(x + off);
      float4 yv = *reinterpret_cast<const float4*>(seg1 + ln*324 + j);
      *reinterpret_cast<float4*>(out + off) =
        make_float4(xr.x+yv.x, xr.y+yv.y, xr.z+yv.z, xr.w+yv.w);
    }
  }
}

static double compute_cssp_host(){
  const int NP = 200001;
  const double LOG2 = 0.6931471805599453094172321214581766;
  double s = 0.0;
  for (int i=0;i<NP;i++){
    double z = -10.0 + (20.0 * i) / (NP - 1);
    double phi = exp(-0.5*z*z) / sqrt(2.0*3.14159265358979323846);
    double sp  = (z > 0.0) ? (z + log1p(exp(-z))) : log1p(exp(z));
    double f   = sp - LOG2;
    double w   = (i==0 || i==NP-1) ? 0.5 : 1.0;
    s += w * f * f * phi;
  }
  s *= 20.0 / (NP - 1);
  return 1.0 / sqrt(s);
}

extern "C" void kernel_launch(void* const* d_in, const int* in_sizes, int n_in,
                              void* d_out, int out_size) {
  const float* x    = (const float*)d_in[0];
  const float* w1s  = (const float*)d_in[1];
  const float* w1v1 = (const float*)d_in[2];
  const float* w1v2 = (const float*)d_in[3];
  const float* w2s  = (const float*)d_in[4];
  const float* w2v1 = (const float*)d_in[5];
  const float* w2v2 = (const float*)d_in[6];
  float* out = (float*)d_out;

  int n = in_sizes[0] / 960;

  static bool attr_done = false;
  if (!attr_done){
    cudaFuncSetAttribute(resblk_kernel,
        cudaFuncAttributeMaxDynamicSharedMemorySize, SMEM_FLOATS*4);
    attr_done = true;
  }
  static const float cssp = (float)compute_cssp_host();

  prep_weights<<<(WBUF_SZ + NT - 1)/NT, NT>>>(w1s, w1v1, w1v2, w2s, w2v1, w2v2);
  resblk_kernel<<<n/TILE, NT, SMEM_FLOATS*4>>>(x, out, cssp);
}

// round 7
// speedup vs baseline: 1.0206x; 1.0206x over previous
#include <cuda_runtime.h>
#include <cstdint>
#include <math.h>

#define NT 512
#define TILE 64
#define G_OFF    25344        // seg1 size: 192*132 floats
#define SMEM_FLOATS 37888     // seg1 + G (64*196)  = 151552 bytes

// Pre-converted tf32 weights, permuted per-k8-chunk N-major (filled by prep_weights)
#define W1S_OFF   0
#define W2S_OFF   114688
#define W1V1_OFF  180224
#define W2V1_OFF  196608
#define W1V2_OFF  212992
#define W2V2_OFF  217088
#define WBUF_SZ   221184
__device__ float WBUF[WBUF_SZ];

static __device__ __forceinline__ float f2tff(float f){
  uint32_t u; asm("cvt.rna.tf32.f32 %0, %1;" : "=r"(u) : "f"(f));
  return __uint_as_float(u);
}

static __device__ __forceinline__ void mma8(float* d, uint32_t a0, uint32_t a1,
                                            uint32_t a2, uint32_t a3,
                                            uint32_t b0, uint32_t b1){
  asm volatile("mma.sync.aligned.m16n8k8.row.col.f32.tf32.tf32.f32 "
      "{%0,%1,%2,%3}, {%4,%5,%6,%7}, {%8,%9}, {%0,%1,%2,%3};"
      : "+f"(d[0]), "+f"(d[1]), "+f"(d[2]), "+f"(d[3])
      : "r"(a0), "r"(a1), "r"(a2), "r"(a3), "r"(b0), "r"(b1));
}

// One ldmatrix.x4 = whole 16x8 tf32 A fragment (a0..a3) for one m16 tile.
static __device__ __forceinline__ void ldsm4(uint32_t* r, uint32_t addr){
  asm volatile("ldmatrix.sync.aligned.m8n8.x4.shared.b16 {%0,%1,%2,%3}, [%4];"
      : "=r"(r[0]), "=r"(r[1]), "=r"(r[2]), "=r"(r[3]) : "r"(addr));
}

// ---------------------------------------------------------------------------
// Init kernel: tf32-convert + permute weights into k8-chunked N-major layout:
//   WBUF[off + kc*N*8 + n*8 + w] = tf32( W[(kc*8 + (w&1)*4 + (w>>1)) * N + n] )
// ---------------------------------------------------------------------------
__global__ void prep_weights(const float* __restrict__ w1s,
                             const float* __restrict__ w1v1,
                             const float* __restrict__ w1v2,
                             const float* __restrict__ w2s,
                             const float* __restrict__ w2v1,
                             const float* __restrict__ w2v2)
{
  int idx = blockIdx.x * blockDim.x + threadIdx.x;
  if (idx >= WBUF_SZ) return;
  const float* src; int N, loc;
  if      (idx < W2S_OFF)  { src = w1s;  N = 448; loc = idx - W1S_OFF;  }
  else if (idx < W1V1_OFF) { src = w2s;  N = 256; loc = idx - W2S_OFF;  }
  else if (idx < W2V1_OFF) { src = w1v1; N = 128; loc = idx - W1V1_OFF; }
  else if (idx < W1V2_OFF) { src = w2v1; N = 128; loc = idx - W2V1_OFF; }
  else if (idx < W2V2_OFF) { src = w1v2; N = 64;  loc = idx - W1V2_OFF; }
  else                     { src = w2v2; N = 64;  loc = idx - W2V2_OFF; }
  int kc = loc / (N*8); int r = loc - kc*N*8; int n = r >> 3; int w = r & 7;
  int k = kc*8 + (w&1)*4 + (w>>1);
  WBUF[idx] = f2tff(src[k*N + n]);
}

// ---------------------------------------------------------------------------
// acc += A(SMEM tf32, pitch PA, ldmatrix.x4, distance-1 pipe)
//      @ B(WBUF k8-packed, LDG.64).
// PB=true : B register-double-buffered one k8-step ahead (distance-1).
// PB=false: B loaded at step start (burst, MLP=WN) — used when WN is large
//           and 4 warps share identical B addresses (L1 hits for 3 of 4).
// ---------------------------------------------------------------------------
template<int K, int N, int WM, int WN, int PA, bool PB>
static __device__ __forceinline__ void run_gemm(const float* __restrict__ gB,
                  uint32_t As_u32, float* acc, int lane, int mi, int nj)
{
  constexpr int NK8 = K/8;
  const float2* __restrict__ bp = reinterpret_cast<const float2*>(gB)
      + (lane & 3) + ((nj*WN)*8 + (lane>>2))*4;
  const int g = lane >> 3, r = lane & 7;
  const uint32_t aaddr = As_u32
      + ((uint32_t)(((mi*WM)*16 + r + (g&1)*8)*PA + (g>>1)*4))*4u;

  float2   b[PB?2:1][WN];
  uint32_t a[2][WM][4];
  if (PB){
    #pragma unroll
    for (int wn=0; wn<WN; wn++) b[0][wn] = __ldg(bp + wn*32);
  }
  #pragma unroll
  for (int wm=0; wm<WM; wm++) ldsm4(a[0][wm], aaddr + wm*(16*PA*4));

  #pragma unroll 4
  for (int kc=0; kc<NK8; kc++){
    const int cur = kc & 1, nxt = cur ^ 1;
    if (PB){
      if (kc+1 < NK8){
        #pragma unroll
        for (int wn=0; wn<WN; wn++) b[nxt][wn] = __ldg(bp + (kc+1)*(N*4) + wn*32);
      }
    } else {
      #pragma unroll
      for (int wn=0; wn<WN; wn++) b[0][wn] = __ldg(bp + kc*(N*4) + wn*32);
    }
    if (kc+1 < NK8){
      #pragma unroll
      for (int wm=0; wm<WM; wm++)
        ldsm4(a[nxt][wm], aaddr + wm*(16*PA*4) + (kc+1)*32);
    }
    #pragma unroll
    for (int wn=0; wn<WN; wn++){
      const int cb = PB ? cur : 0;
      uint32_t b0 = __float_as_uint(b[cb][wn].x);
      uint32_t b1 = __float_as_uint(b[cb][wn].y);
      #pragma unroll
      for (int wm=0; wm<WM; wm++)
        mma8(acc+(wm*WN+wn)*4, a[cur][wm][0],a[cur][wm][1],
             a[cur][wm][2],a[cur][wm][3], b0, b1);
    }
  }
}

static __device__ __forceinline__ float sspf(float v, float cssp){
  float sp = fmaxf(v, 0.0f) + log1pf(expf(-fabsf(v)));
  return cssp * (sp - 0.69314718055994531f);
}

__global__ void __launch_bounds__(NT, 1)
resblk_kernel(const float* __restrict__ x, float* __restrict__ out, float cssp)
{
  extern __shared__ float sm[];
  float* seg1 = sm;
  float* G    = sm + G_OFF;
  uint32_t sm_u32;
  { uint32_t a; asm("{ .reg .u64 t; cvta.to.shared.u64 t, %1; cvt.u32.u64 %0, t; }"
                    : "=r"(a) : "l"(sm)); sm_u32 = a; }

  const int tid  = threadIdx.x;
  const int lane = tid & 31;
  const int warp = tid >> 5;
  const int mi4  = warp >> 2;     // 4M x 4N grid (ALL GEMMs): 4-way B sharing
  const int nj4  = warp & 3;
  const int n0   = blockIdx.x * TILE;
  const float RS128 = 0.08838834764831845f;
  const float RS64  = 0.125f;

  // ================= scalar path =================
  // A0 = tf32(x0 tile)  [64 x 256], pitch 260
  for (int t=tid; t<(TILE*256)/4; t+=NT){
    int e=t*4; int ln=e>>8; int col=e&255;
    float4 v = *reinterpret_cast<const float4*>(x + (size_t)(n0+ln)*960 + col);
    *reinterpret_cast<float4*>(seg1 + ln*260 + col) =
      make_float4(f2tff(v.x),f2tff(v.y),f2tff(v.z),f2tff(v.w));
  }
  __syncthreads();
  // s = A0 @ w1s / 16, SSP -> scalars(seg1, tf32) + gates(G, fp32)
  {
    float acc[56];
    #pragma unroll
    for (int i=0;i<56;i++) acc[i]=0.f;
    run_gemm<256,448,1,14,260,false>(&WBUF[W1S_OFF], sm_u32, acc, lane, mi4, nj4);
    __syncthreads();
    #pragma unroll
    for (int wn=0; wn<14; wn++){
      #pragma unroll
      for (int q=0;q<4;q++){
        int row = mi4*16 + (lane>>2) + ((q&2)<<2);
        int col = (nj4*14+wn)*8 + ((lane&3)<<1) + (q&1);
        float h = sspf(acc[wn*4+q]*0.0625f, cssp);
        if (col < 256) seg1[row*260 + col] = f2tff(h);
        else           G[row*196 + (col-256)] = h;
      }
    }
  }
  __syncthreads();
  // y0 = scalars @ w2s / 16 ; stage then coalesced residual write
  {
    float acc[32];
    #pragma unroll
    for (int i=0;i<32;i++) acc[i]=0.f;
    run_gemm<256,256,1,8,260,true>(&WBUF[W2S_OFF], sm_u32, acc, lane, mi4, nj4);
    __syncthreads();
    #pragma unroll
    for (int wn=0; wn<8; wn++){
      #pragma unroll
      for (int q=0;q<4;q++){
        int row = mi4*16 + (lane>>2) + ((q&2)<<2);
        int col = (nj4*8+wn)*8 + ((lane&3)<<1) + (q&1);
        seg1[row*260 + col] = acc[wn*4+q]*0.0625f;
      }
    }
    __syncthreads();
    for (int t=tid; t<TILE*64; t+=NT){
      int ln=t>>6; int j=(t&63)*4;
      size_t off = (size_t)(n0+ln)*960 + j;
      float4 xr = *reinterpret_cast<const float4*>(x + off);
      float4 yv = *reinterpret_cast<const float4*>(seg1 + ln*260 + j);
      *reinterpret_cast<float4*>(out + off) =
        make_float4(xr.x+yv.x, xr.y+yv.y, xr.z+yv.z, xr.w+yv.w);
    }
  }
  __syncthreads();

  // ================= v1 path =================
  // A1[c*64+n][i] = tf32(x[n, 256+3i+c])  [192 x 128], pitch 132
  for (int t=tid; t<(TILE*384)/4; t+=NT){
    int e=t*4; int ln=e/384; int j=e-ln*384;
    float4 v = *reinterpret_cast<const float4*>(x + (size_t)(n0+ln)*960 + 256 + j);
    float vv[4]={v.x,v.y,v.z,v.w};
    #pragma unroll
    for (int q=0;q<4;q++){
      int jj=j+q; int i3=jj/3; int c=jj-i3*3;
      seg1[(c*64+ln)*132 + i3] = f2tff(vv[q]);
    }
  }
  __syncthreads();
  // V1 = A1 @ w1v1 * rs128, gated, in place (tf32)
  {
    float acc[48];
    #pragma unroll
    for (int i=0;i<48;i++) acc[i]=0.f;
    run_gemm<128,128,3,4,132,true>(&WBUF[W1V1_OFF], sm_u32, acc, lane, mi4, nj4);
    __syncthreads();
    #pragma unroll
    for (int wm=0; wm<3; wm++){
      #pragma unroll
      for (int wn=0; wn<4; wn++){
        #pragma unroll
        for (int q=0;q<4;q++){
          int row = (mi4*3+wm)*16 + (lane>>2) + ((q&2)<<2);
          int col = (nj4*4+wn)*8 + ((lane&3)<<1) + (q&1);
          float g = G[(row&63)*196 + col];
          seg1[row*132 + col] = f2tff(acc[(wm*4+wn)*4+q]*RS128*g);
        }
      }
    }
  }
  __syncthreads();
  // Y1 = V1 @ w2v1 * rs128 -> stage [n][3o+c] -> coalesced residual write
  {
    float acc[48];
    #pragma unroll
    for (int i=0;i<48;i++) acc[i]=0.f;
    run_gemm<128,128,3,4,132,true>(&WBUF[W2V1_OFF], sm_u32, acc, lane, mi4, nj4);
    __syncthreads();
    #pragma unroll
    for (int wm=0; wm<3; wm++){
      #pragma unroll
      for (int wn=0; wn<4; wn++){
        #pragma unroll
        for (int q=0;q<4;q++){
          int row = (mi4*3+wm)*16 + (lane>>2) + ((q&2)<<2);
          int col = (nj4*4+wn)*8 + ((lane&3)<<1) + (q&1);
          int n = row & 63; int c = row >> 6;
          seg1[n*388 + 3*col + c] = acc[(wm*4+wn)*4+q]*RS128;
        }
      }
    }
    __syncthreads();
    for (int t=tid; t<TILE*96; t+=NT){
      int ln=t/96; int j=(t-ln*96)*4;
      size_t off = (size_t)(n0+ln)*960 + 256 + j;
      float4 xr = *reinterpret_cast<const float4*>(x + off);
      float4 yv = *reinterpret_cast<const float4*>(seg1 + ln*388 + j);
      *reinterpret_cast<float4*>(out + off) =
        make_float4(xr.x+yv.x, xr.y+yv.y, xr.z+yv.z, xr.w+yv.w);
    }
  }
  __syncthreads();

  // ================= v2 path =================
  // A2[c*64+n][i] = tf32(x[n, 640+5i+c])  [320 x 64], pitch 68
  for (int t=tid; t<(TILE*320)/4; t+=NT){
    int e=t*4; int ln=e/320; int j=e-ln*320;
    float4 v = *reinterpret_cast<const float4*>(x + (size_t)(n0+ln)*960 + 640 + j);
    float vv[4]={v.x,v.y,v.z,v.w};
    #pragma unroll
    for (int q=0;q<4;q++){
      int jj=j+q; int i5=jj/5; int c=jj-i5*5;
      seg1[(c*64+ln)*68 + i5] = f2tff(vv[q]);
    }
  }
  __syncthreads();
  // V2 = A2 @ w1v2 * rs64, gated, in place (tf32)
  {
    float acc[40];
    #pragma unroll
    for (int i=0;i<40;i++) acc[i]=0.f;
    run_gemm<64,64,5,2,68,true>(&WBUF[W1V2_OFF], sm_u32, acc, lane, mi4, nj4);
    __syncthreads();
    #pragma unroll
    for (int wm=0; wm<5; wm++){
      #pragma unroll
      for (int wn=0; wn<2; wn++){
        #pragma unroll
        for (int q=0;q<4;q++){
          int row = (mi4*5+wm)*16 + (lane>>2) + ((q&2)<<2);
          int col = (nj4*2+wn)*8 + ((lane&3)<<1) + (q&1);
          float g = G[(row&63)*196 + 128 + col];
          seg1[row*68 + col] = f2tff(acc[(wm*2+wn)*4+q]*RS64*g);
        }
      }
    }
  }
  __syncthreads();
  // Y2 = V2 @ w2v2 * rs64 -> stage [n][5o+c] -> coalesced residual write
  {
    float acc[40];
    #pragma unroll
    for (int i=0;i<40;i++) acc[i]=0.f;
    run_gemm<64,64,5,2,68,true>(&WBUF[W2V2_OFF], sm_u32, acc, lane, mi4, nj4);
    __syncthreads();
    #pragma unroll
    for (int wm=0; wm<5; wm++){
      #pragma unroll
      for (int wn=0; wn<2; wn++){
        #pragma unroll
        for (int q=0;q<4;q++){
          int row = (mi4*5+wm)*16 + (lane>>2) + ((q&2)<<2);
          int col = (nj4*2+wn)*8 + ((lane&3)<<1) + (q&1);
          int n = row & 63; int c = row >> 6;
          seg1[n*324 + 5*col + c] = acc[(wm*2+wn)*4+q]*RS64;
        }
      }
    }
    __syncthreads();
    for (int t=tid; t<TILE*80; t+=NT){
      int ln=t/80; int j=(t-ln*80)*4;
      size_t off = (size_t)(n0+ln)*960 + 640 + j;
      float4 xr = *reinterpret_cast<const float4*>(x + off);
      float4 yv = *reinterpret_cast<const float4*>(seg1 + ln*324 + j);
      *reinterpret_cast<float4*>(out + off) =
        make_float4(xr.x+yv.x, xr.y+yv.y, xr.z+yv.z, xr.w+yv.w);
    }
  }
}

static double compute_cssp_host(){
  const int NP = 200001;
  const double LOG2 = 0.6931471805599453094172321214581766;
  double s = 0.0;
  for (int i=0;i<NP;i++){
    double z = -10.0 + (20.0 * i) / (NP - 1);
    double phi = exp(-0.5*z*z) / sqrt(2.0*3.14159265358979323846);
    double sp  = (z > 0.0) ? (z + log1p(exp(-z))) : log1p(exp(z));
    double f   = sp - LOG2;
    double w   = (i==0 || i==NP-1) ? 0.5 : 1.0;
    s += w * f * f * phi;
  }
  s *= 20.0 / (NP - 1);
  return 1.0 / sqrt(s);
}

extern "C" void kernel_launch(void* const* d_in, const int* in_sizes, int n_in,
                              void* d_out, int out_size) {
  const float* x    = (const float*)d_in[0];
  const float* w1s  = (const float*)d_in[1];
  const float* w1v1 = (const float*)d_in[2];
  const float* w1v2 = (const float*)d_in[3];
  const float* w2s  = (const float*)d_in[4];
  const float* w2v1 = (const float*)d_in[5];
  const float* w2v2 = (const float*)d_in[6];
  float* out = (float*)d_out;

  int n = in_sizes[0] / 960;

  static bool attr_done = false;
  if (!attr_done){
    cudaFuncSetAttribute(resblk_kernel,
        cudaFuncAttributeMaxDynamicSharedMemorySize, SMEM_FLOATS*4);
    attr_done = true;
  }
  static const float cssp = (float)compute_cssp_host();

  prep_weights<<<(WBUF_SZ + NT - 1)/NT, NT>>>(w1s, w1v1, w1v2, w2s, w2v1, w2v2);
  resblk_kernel<<<n/TILE, NT, SMEM_FLOATS*4>>>(x, out, cssp);
}

// round 8
// speedup vs baseline: 1.2398x; 1.2148x over previous
#include <cuda_runtime.h>
#include <cstdint>
#include <math.h>

#define NT 256
#define TILE 32
#define G_OFF    12672        // seg1 size: 96*132 floats (v1 A-tile is largest)
#define SMEM_FLOATS 18944     // seg1 + G (32*196)  = 75776 bytes

// Pre-converted tf32 weights, permuted per-k8-chunk N-major (filled by prep_weights)
#define W1S_OFF   0
#define W2S_OFF   114688
#define W1V1_OFF  180224
#define W2V1_OFF  196608
#define W1V2_OFF  212992
#define W2V2_OFF  217088
#define WBUF_SZ   221184
__device__ float WBUF[WBUF_SZ];

static __device__ __forceinline__ float f2tff(float f){
  uint32_t u; asm("cvt.rna.tf32.f32 %0, %1;" : "=r"(u) : "f"(f));
  return __uint_as_float(u);
}

static __device__ __forceinline__ void mma8(float* d, uint32_t a0, uint32_t a1,
                                            uint32_t a2, uint32_t a3,
                                            uint32_t b0, uint32_t b1){
  asm volatile("mma.sync.aligned.m16n8k8.row.col.f32.tf32.tf32.f32 "
      "{%0,%1,%2,%3}, {%4,%5,%6,%7}, {%8,%9}, {%0,%1,%2,%3};"
      : "+f"(d[0]), "+f"(d[1]), "+f"(d[2]), "+f"(d[3])
      : "r"(a0), "r"(a1), "r"(a2), "r"(a3), "r"(b0), "r"(b1));
}

// One ldmatrix.x4 = whole 16x8 tf32 A fragment (a0..a3) for one m16 tile.
static __device__ __forceinline__ void ldsm4(uint32_t* r, uint32_t addr){
  asm volatile("ldmatrix.sync.aligned.m8n8.x4.shared.b16 {%0,%1,%2,%3}, [%4];"
      : "=r"(r[0]), "=r"(r[1]), "=r"(r[2]), "=r"(r[3]) : "r"(addr));
}

// ---------------------------------------------------------------------------
// Init kernel: tf32-convert + permute weights into k8-chunked N-major layout:
//   WBUF[off + kc*N*8 + n*8 + w] = tf32( W[(kc*8 + (w&1)*4 + (w>>1)) * N + n] )
// ---------------------------------------------------------------------------
__global__ void prep_weights(const float* __restrict__ w1s,
                             const float* __restrict__ w1v1,
                             const float* __restrict__ w1v2,
                             const float* __restrict__ w2s,
                             const float* __restrict__ w2v1,
                             const float* __restrict__ w2v2)
{
  int idx = blockIdx.x * blockDim.x + threadIdx.x;
  if (idx >= WBUF_SZ) return;
  const float* src; int N, loc;
  if      (idx < W2S_OFF)  { src = w1s;  N = 448; loc = idx - W1S_OFF;  }
  else if (idx < W1V1_OFF) { src = w2s;  N = 256; loc = idx - W2S_OFF;  }
  else if (idx < W2V1_OFF) { src = w1v1; N = 128; loc = idx - W1V1_OFF; }
  else if (idx < W1V2_OFF) { src = w2v1; N = 128; loc = idx - W2V1_OFF; }
  else if (idx < W2V2_OFF) { src = w1v2; N = 64;  loc = idx - W1V2_OFF; }
  else                     { src = w2v2; N = 64;  loc = idx - W2V2_OFF; }
  int kc = loc / (N*8); int r = loc - kc*N*8; int n = r >> 3; int w = r & 7;
  int k = kc*8 + (w&1)*4 + (w>>1);
  WBUF[idx] = f2tff(src[k*N + n]);
}

// ---------------------------------------------------------------------------
// acc += A(SMEM tf32, pitch PA, ldmatrix.x4, distance-1 pipe)
//      @ B(WBUF k8-packed, LDG.64, distance-1 register double-buffer).
// Proven R5 shape. No barriers inside.
// ---------------------------------------------------------------------------
template<int K, int N, int WM, int WN, int PA>
static __device__ __forceinline__ void run_gemm(const float* __restrict__ gB,
                  uint32_t As_u32, float* acc, int lane, int mi, int nj)
{
  constexpr int NK8 = K/8;
  const float2* __restrict__ bp = reinterpret_cast<const float2*>(gB)
      + (lane & 3) + ((nj*WN)*8 + (lane>>2))*4;
  const int g = lane >> 3, r = lane & 7;
  const uint32_t aaddr = As_u32
      + ((uint32_t)(((mi*WM)*16 + r + (g&1)*8)*PA + (g>>1)*4))*4u;

  float2   b[2][WN];
  uint32_t a[2][WM][4];
  #pragma unroll
  for (int wn=0; wn<WN; wn++) b[0][wn] = __ldg(bp + wn*32);
  #pragma unroll
  for (int wm=0; wm<WM; wm++) ldsm4(a[0][wm], aaddr + wm*(16*PA*4));

  #pragma unroll 4
  for (int kc=0; kc<NK8; kc++){
    const int cur = kc & 1, nxt = cur ^ 1;
    if (kc+1 < NK8){
      #pragma unroll
      for (int wn=0; wn<WN; wn++) b[nxt][wn] = __ldg(bp + (kc+1)*(N*4) + wn*32);
      #pragma unroll
      for (int wm=0; wm<WM; wm++) ldsm4(a[nxt][wm], aaddr + wm*(16*PA*4) + (kc+1)*32);
    }
    #pragma unroll
    for (int wn=0; wn<WN; wn++){
      uint32_t b0 = __float_as_uint(b[cur][wn].x);
      uint32_t b1 = __float_as_uint(b[cur][wn].y);
      #pragma unroll
      for (int wm=0; wm<WM; wm++)
        mma8(acc+(wm*WN+wn)*4, a[cur][wm][0],a[cur][wm][1],
             a[cur][wm][2],a[cur][wm][3], b0, b1);
    }
  }
}

static __device__ __forceinline__ float sspf(float v, float cssp){
  float sp = fmaxf(v, 0.0f) + log1pf(expf(-fabsf(v)));
  return cssp * (sp - 0.69314718055994531f);
}

__global__ void __launch_bounds__(NT, 2)
resblk_kernel(const float* __restrict__ x, float* __restrict__ out, float cssp)
{
  extern __shared__ float sm[];
  float* seg1 = sm;
  float* G    = sm + G_OFF;
  uint32_t sm_u32;
  { uint32_t a; asm("{ .reg .u64 t; cvta.to.shared.u64 t, %1; cvt.u32.u64 %0, t; }"
                    : "=r"(a) : "l"(sm)); sm_u32 = a; }

  const int tid  = threadIdx.x;
  const int lane = tid & 31;
  const int warp = tid >> 5;            // 0..7
  const int nj2  = warp;                // scalar path: 1M x 8N
  const int mi4  = warp >> 2;           // vector paths: 2M x 4N
  const int nj4  = warp & 3;
  const int n0   = blockIdx.x * TILE;
  const float RS128 = 0.08838834764831845f;
  const float RS64  = 0.125f;

  // ================= scalar path =================
  // A0 = tf32(x0 tile)  [32 x 256], pitch 260
  for (int t=tid; t<(TILE*256)/4; t+=NT){
    int e=t*4; int ln=e>>8; int col=e&255;
    float4 v = *reinterpret_cast<const float4*>(x + (size_t)(n0+ln)*960 + col);
    *reinterpret_cast<float4*>(seg1 + ln*260 + col) =
      make_float4(f2tff(v.x),f2tff(v.y),f2tff(v.z),f2tff(v.w));
  }
  __syncthreads();
  // s = A0 @ w1s / 16, SSP -> scalars(seg1, tf32) + gates(G, fp32)
  {
    float acc[56];
    #pragma unroll
    for (int i=0;i<56;i++) acc[i]=0.f;
    run_gemm<256,448,2,7,260>(&WBUF[W1S_OFF], sm_u32, acc, lane, 0, nj2);
    __syncthreads();
    #pragma unroll
    for (int wm=0; wm<2; wm++){
      #pragma unroll
      for (int wn=0; wn<7; wn++){
        #pragma unroll
        for (int q=0;q<4;q++){
          int row = wm*16 + (lane>>2) + ((q&2)<<2);
          int col = (nj2*7+wn)*8 + ((lane&3)<<1) + (q&1);
          float h = sspf(acc[(wm*7+wn)*4+q]*0.0625f, cssp);
          if (col < 256) seg1[row*260 + col] = f2tff(h);
          else           G[row*196 + (col-256)] = h;
        }
      }
    }
  }
  __syncthreads();
  // y0 = scalars @ w2s / 16 ; stage then coalesced residual write
  {
    float acc[32];
    #pragma unroll
    for (int i=0;i<32;i++) acc[i]=0.f;
    run_gemm<256,256,2,4,260>(&WBUF[W2S_OFF], sm_u32, acc, lane, 0, nj2);
    __syncthreads();
    #pragma unroll
    for (int wm=0; wm<2; wm++){
      #pragma unroll
      for (int wn=0; wn<4; wn++){
        #pragma unroll
        for (int q=0;q<4;q++){
          int row = wm*16 + (lane>>2) + ((q&2)<<2);
          int col = (nj2*4+wn)*8 + ((lane&3)<<1) + (q&1);
          seg1[row*260 + col] = acc[(wm*4+wn)*4+q]*0.0625f;
        }
      }
    }
    __syncthreads();
    for (int t=tid; t<TILE*64; t+=NT){
      int ln=t>>6; int j=(t&63)*4;
      size_t off = (size_t)(n0+ln)*960 + j;
      float4 xr = *reinterpret_cast<const float4*>(x + off);
      float4 yv = *reinterpret_cast<const float4*>(seg1 + ln*260 + j);
      *reinterpret_cast<float4*>(out + off) =
        make_float4(xr.x+yv.x, xr.y+yv.y, xr.z+yv.z, xr.w+yv.w);
    }
  }
  __syncthreads();

  // ================= v1 path =================
  // A1[c*32+n][i] = tf32(x[n, 256+3i+c])  [96 x 128], pitch 132
  for (int t=tid; t<(TILE*384)/4; t+=NT){
    int e=t*4; int ln=e/384; int j=e-ln*384;
    float4 v = *reinterpret_cast<const float4*>(x + (size_t)(n0+ln)*960 + 256 + j);
    float vv[4]={v.x,v.y,v.z,v.w};
    #pragma unroll
    for (int q=0;q<4;q++){
      int jj=j+q; int i3=jj/3; int c=jj-i3*3;
      seg1[(c*32+ln)*132 + i3] = f2tff(vv[q]);
    }
  }
  __syncthreads();
  // V1 = A1 @ w1v1 * rs128, gated, in place (tf32)
  {
    float acc[48];
    #pragma unroll
    for (int i=0;i<48;i++) acc[i]=0.f;
    run_gemm<128,128,3,4,132>(&WBUF[W1V1_OFF], sm_u32, acc, lane, mi4, nj4);
    __syncthreads();
    #pragma unroll
    for (int wm=0; wm<3; wm++){
      #pragma unroll
      for (int wn=0; wn<4; wn++){
        #pragma unroll
        for (int q=0;q<4;q++){
          int row = (mi4*3+wm)*16 + (lane>>2) + ((q&2)<<2);
          int col = (nj4*4+wn)*8 + ((lane&3)<<1) + (q&1);
          float g = G[(row&31)*196 + col];
          seg1[row*132 + col] = f2tff(acc[(wm*4+wn)*4+q]*RS128*g);
        }
      }
    }
  }
  __syncthreads();
  // Y1 = V1 @ w2v1 * rs128 -> stage [n][3o+c] -> coalesced residual write
  {
    float acc[48];
    #pragma unroll
    for (int i=0;i<48;i++) acc[i]=0.f;
    run_gemm<128,128,3,4,132>(&WBUF[W2V1_OFF], sm_u32, acc, lane, mi4, nj4);
    __syncthreads();
    #pragma unroll
    for (int wm=0; wm<3; wm++){
      #pragma unroll
      for (int wn=0; wn<4; wn++){
        #pragma unroll
        for (int q=0;q<4;q++){
          int row = (mi4*3+wm)*16 + (lane>>2) + ((q&2)<<2);
          int col = (nj4*4+wn)*8 + ((lane&3)<<1) + (q&1);
          int n = row & 31; int c = row >> 5;
          seg1[n*388 + 3*col + c] = acc[(wm*4+wn)*4+q]*RS128;
        }
      }
    }
    __syncthreads();
    for (int t=tid; t<TILE*96; t+=NT){
      int ln=t/96; int j=(t-ln*96)*4;
      size_t off = (size_t)(n0+ln)*960 + 256 + j;
      float4 xr = *reinterpret_cast<const float4*>(x + off);
      float4 yv = *reinterpret_cast<const float4*>(seg1 + ln*388 + j);
      *reinterpret_cast<float4*>(out + off) =
        make_float4(xr.x+yv.x, xr.y+yv.y, xr.z+yv.z, xr.w+yv.w);
    }
  }
  __syncthreads();

  // ================= v2 path =================
  // A2[c*32+n][i] = tf32(x[n, 640+5i+c])  [160 x 64], pitch 68
  for (int t=tid; t<(TILE*320)/4; t+=NT){
    int e=t*4; int ln=e/320; int j=e-ln*320;
    float4 v = *reinterpret_cast<const float4*>(x + (size_t)(n0+ln)*960 + 640 + j);
    float vv[4]={v.x,v.y,v.z,v.w};
    #pragma unroll
    for (int q=0;q<4;q++){
      int jj=j+q; int i5=jj/5; int c=jj-i5*5;
      seg1[(c*32+ln)*68 + i5] = f2tff(vv[q]);
    }
  }
  __syncthreads();
  // V2 = A2 @ w1v2 * rs64, gated, in place (tf32)
  {
    float acc[40];
    #pragma unroll
    for (int i=0;i<40;i++) acc[i]=0.f;
    run_gemm<64,64,5,2,68>(&WBUF[W1V2_OFF], sm_u32, acc, lane, mi4, nj4);
    __syncthreads();
    #pragma unroll
    for (int wm=0; wm<5; wm++){
      #pragma unroll
      for (int wn=0; wn<2; wn++){
        #pragma unroll
        for (int q=0;q<4;q++){
          int row = (mi4*5+wm)*16 + (lane>>2) + ((q&2)<<2);
          int col = (nj4*2+wn)*8 + ((lane&3)<<1) + (q&1);
          float g = G[(row&31)*196 + 128 + col];
          seg1[row*68 + col] = f2tff(acc[(wm*2+wn)*4+q]*RS64*g);
        }
      }
    }
  }
  __syncthreads();
  // Y2 = V2 @ w2v2 * rs64 -> stage [n][5o+c] -> coalesced residual write
  {
    float acc[40];
    #pragma unroll
    for (int i=0;i<40;i++) acc[i]=0.f;
    run_gemm<64,64,5,2,68>(&WBUF[W2V2_OFF], sm_u32, acc, lane, mi4, nj4);
    __syncthreads();
    #pragma unroll
    for (int wm=0; wm<5; wm++){
      #pragma unroll
      for (int wn=0; wn<2; wn++){
        #pragma unroll
        for (int q=0;q<4;q++){
          int row = (mi4*5+wm)*16 + (lane>>2) + ((q&2)<<2);
          int col = (nj4*2+wn)*8 + ((lane&3)<<1) + (q&1);
          int n = row & 31; int c = row >> 5;
          seg1[n*324 + 5*col + c] = acc[(wm*2+wn)*4+q]*RS64;
        }
      }
    }
    __syncthreads();
    for (int t=tid; t<TILE*80; t+=NT){
      int ln=t/80; int j=(t-ln*80)*4;
      size_t off = (size_t)(n0+ln)*960 + 640 + j;
      float4 xr = *reinterpret_cast<const float4*>(x + off);
      float4 yv = *reinterpret_cast<const float4*>(seg1 + ln*324 + j);
      *reinterpret_cast<float4*>(out + off) =
        make_float4(xr.x+yv.x, xr.y+yv.y, xr.z+yv.z, xr.w+yv.w);
    }
  }
}

static double compute_cssp_host(){
  const int NP = 200001;
  const double LOG2 = 0.6931471805599453094172321214581766;
  double s = 0.0;
  for (int i=0;i<NP;i++){
    double z = -10.0 + (20.0 * i) / (NP - 1);
    double phi = exp(-0.5*z*z) / sqrt(2.0*3.14159265358979323846);
    double sp  = (z > 0.0) ? (z + log1p(exp(-z))) : log1p(exp(z));
    double f   = sp - LOG2;
    double w   = (i==0 || i==NP-1) ? 0.5 : 1.0;
    s += w * f * f * phi;
  }
  s *= 20.0 / (NP - 1);
  return 1.0 / sqrt(s);
}

extern "C" void kernel_launch(void* const* d_in, const int* in_sizes, int n_in,
                              void* d_out, int out_size) {
  const float* x    = (const float*)d_in[0];
  const float* w1s  = (const float*)d_in[1];
  const float* w1v1 = (const float*)d_in[2];
  const float* w1v2 = (const float*)d_in[3];
  const float* w2s  = (const float*)d_in[4];
  const float* w2v1 = (const float*)d_in[5];
  const float* w2v2 = (const float*)d_in[6];
  float* out = (float*)d_out;

  int n = in_sizes[0] / 960;

  static bool attr_done = false;
  if (!attr_done){
    cudaFuncSetAttribute(resblk_kernel,
        cudaFuncAttributeMaxDynamicSharedMemorySize, SMEM_FLOATS*4);
    attr_done = true;
  }
  static const float cssp = (float)compute_cssp_host();

  prep_weights<<<(WBUF_SZ + NT - 1)/NT, NT>>>(w1s, w1v1, w1v2, w2s, w2v1, w2v2);
  resblk_kernel<<<n/TILE, NT, SMEM_FLOATS*4>>>(x, out, cssp);
}